// round 7
// baseline (speedup 1.0000x reference)
#include <cuda_runtime.h>

// BeliefMatchingLoss: pred [8,19,512,512] f32, target [8,512,512] int32 -> scalar f32
// Single-kernel last-block reduction; self-resetting for graph replay.
//
// loss_pix = 0.01*kl + psi(a0) - psi(a_ans)
// kl = lnG(a0) - (a0-19)*psi(a0) + sum_c g(a_c),  a_c = exp(p_c), a0 = sum a_c
// Per-class g via shift-1 (z=x+1, u=1/z), using ln x = p exactly:
//   g ~= p + 1/x + z - 1.5*ln z + (5/6)u + (1/6)u^2 + u^3/90 - (C+1.5)
// (error <~2e-2 only for rare tiny x; contributes O(1e-4) to the final loss
//  through the 0.01 coefficient -- tolerance is 1e-3)
// One rcp r=1/(x*z) per class gives u=x*r and 1/x=z*r; rcp batched per class
// pair; lg2 of z batched in groups of <=8. Packed 2 px/thread via fma.rn.f32x2.
// psi(a0), lnG(a0), psi(x_ans) use the accurate shift-2 scalar path.

typedef unsigned long long u64;

#define HW_   (512 * 512)
#define NC_   19
#define NPIX_ (8 * HW_)
#define NTHR_ (NPIX_ / 2)
#define NBLK_ (NTHR_ / 256)

#define LN2F        0.6931471805599453f
#define LOG2EF      1.4426950408889634f
#define HALF_LN_2PI 0.91893853320467274f

__device__ double             g_sum    = 0.0;
__device__ unsigned long long g_cnt    = 0ull;
__device__ unsigned int       g_arrive = 0u;

// ---- packed f32x2 helpers (u64 = {lo,hi} fp32 pair) ----
__device__ __forceinline__ u64 pk2(float a, float b) {
    u64 r; asm("mov.b64 %0,{%1,%2};" : "=l"(r) : "f"(a), "f"(b)); return r;
}
__device__ __forceinline__ void upk2(u64 v, float& a, float& b) {
    asm("mov.b64 {%0,%1},%2;" : "=f"(a), "=f"(b) : "l"(v));
}
__device__ __forceinline__ u64 f2fma(u64 a, u64 b, u64 c) {
    u64 d; asm("fma.rn.f32x2 %0,%1,%2,%3;" : "=l"(d) : "l"(a), "l"(b), "l"(c)); return d;
}
__device__ __forceinline__ u64 f2mul(u64 a, u64 b) {
    u64 d; asm("mul.rn.f32x2 %0,%1,%2;" : "=l"(d) : "l"(a), "l"(b)); return d;
}
__device__ __forceinline__ u64 f2add(u64 a, u64 b) {
    u64 d; asm("add.rn.f32x2 %0,%1,%2;" : "=l"(d) : "l"(a), "l"(b)); return d;
}
__device__ __forceinline__ float ex2f(float x) { float r; asm("ex2.approx.f32 %0,%1;" : "=f"(r) : "f"(x)); return r; }
__device__ __forceinline__ float lg2f_(float x){ float r; asm("lg2.approx.f32 %0,%1;" : "=f"(r) : "f"(x)); return r; }
__device__ __forceinline__ float rcpf_(float x){ float r; asm("rcp.approx.f32 %0,%1;" : "=f"(r) : "f"(x)); return r; }
__device__ __forceinline__ u64 rcp_2(u64 v) { float a, b; upk2(v, a, b); return pk2(rcpf_(a), rcpf_(b)); }

// scalar digamma+lgamma, shift-2 (accurate; once per pixel on a0 >= ~5)
__device__ __forceinline__ void psi_lg_s(float x, float& psi, float& lg) {
    float z   = x + 2.0f;
    float P   = fmaf(x, x, x);
    float r   = rcpf_(P * z);
    float S   = fmaf(2.0f, P, fmaf(3.0f, x, 2.0f)) * r;
    float rz  = P * r;
    float rz2 = rz * rz;
    float lnz = lg2f_(z) * LN2F;
    float lnP = lg2f_(P) * LN2F;
    float c = fmaf(rz, 0.5f, rz2 * fmaf(rz2, -1.0f / 120.0f, 1.0f / 12.0f));
    float t = rz * fmaf(rz2, -1.0f / 360.0f, 1.0f / 12.0f);
    psi = lnz - c - S;
    lg  = fmaf(z - 0.5f, lnz, -z) + HALF_LN_2PI + t - lnP;
}

// scalar digamma only, shift-2 (accurate down to tiny x; once per pixel on x_ans)
__device__ __forceinline__ float psi_s(float x) {
    float z   = x + 2.0f;
    float P   = fmaf(x, x, x);
    float r   = rcpf_(P * z);
    float S   = fmaf(2.0f, P, fmaf(3.0f, x, 2.0f)) * r;
    float rz  = P * r;
    float rz2 = rz * rz;
    float c = fmaf(rz, 0.5f, rz2 * fmaf(rz2, -1.0f / 120.0f, 1.0f / 12.0f));
    return lg2f_(z) * LN2F - c - S;
}

__global__ __launch_bounds__(256, 4) void bml_main(const float* __restrict__ pred,
                                                   const int*  __restrict__ tgt,
                                                   float*      __restrict__ out) {
    int tix = blockIdx.x * 256 + threadIdx.x;
    int pix = tix * 2;
    int b   = pix >> 18;
    int hw  = pix & (HW_ - 1);
    const float* pp = pred + (size_t)b * NC_ * HW_ + hw;

    int2 tv  = *reinterpret_cast<const int2*>(tgt + pix);
    bool ig0 = (tv.x == 255), ig1 = (tv.y == 255);
    int  ta0 = ig0 ? 0 : tv.x;
    int  ta1 = ig1 ? 0 : tv.y;

    // answer-class gather (these lines are re-touched by the class loop -> cache hits)
    float pa0 = pp[(size_t)ta0 * HW_];
    float pa1 = pp[(size_t)ta1 * HW_ + 1];

    const u64 KL2E = pk2(LOG2EF, LOG2EF);
    const u64 K1   = pk2(1.0f, 1.0f);
    const u64 C90  = pk2(1.0f / 90.0f, 1.0f / 90.0f);
    const u64 C6   = pk2(1.0f / 6.0f, 1.0f / 6.0f);
    const u64 C56  = pk2(5.0f / 6.0f, 5.0f / 6.0f);

    u64 accU = pk2(0.0f, 0.0f);   // sum poly(u)
    u64 accX = accU;              // sum 1/x
    u64 accP = accU;              // sum p  (= sum ln x, exact)
    u64 a0v  = accU;              // sum x
    u64 zp   = K1;                // running z product for batched lnz
    float lgz_lo = 0.0f, lgz_hi = 0.0f;

#define STAGE1(xx, zz, ww, c) do {                                            \
        u64 pv = *reinterpret_cast<const u64*>(pp + (size_t)(c) * HW_);       \
        accP = f2add(accP, pv);                                               \
        u64 e  = f2mul(pv, KL2E);                                             \
        float el, eh; upk2(e, el, eh);                                        \
        (xx) = pk2(ex2f(el), ex2f(eh));                                       \
        (zz) = f2add((xx), K1);                                               \
        (ww) = f2mul((xx), (zz));                                             \
    } while (0)

#define STAGE2(xx, zz, rr) do {                                               \
        u64 u_ = f2mul((xx), (rr));            /* 1/z */                      \
        u64 ix = f2mul((zz), (rr));            /* 1/x */                      \
        u64 q  = f2fma(u_, C90, C6);                                          \
        q      = f2fma(u_, q, C56);                                           \
        accU   = f2fma(u_, q, accU);                                          \
        accX   = f2add(accX, ix);                                             \
        a0v    = f2add(a0v, (xx));                                            \
    } while (0)

#pragma unroll
    for (int k = 0; k < 9; ++k) {
        const int c0 = 2 * k, c1 = 2 * k + 1;
        u64 x0, z0, w0, x1, z1, w1;
        STAGE1(x0, z0, w0, c0);
        STAGE1(x1, z1, w1, c1);
        u64 rr = rcp_2(f2mul(w0, w1));         // 1/(x0 z0 x1 z1)
        u64 r0 = f2mul(rr, w1);
        u64 r1 = f2mul(rr, w0);
        zp = f2mul(zp, f2mul(z0, z1));
        if (k == 3 || k == 7) {                 // 8-class lnz batch
            float zl, zh; upk2(zp, zl, zh);
            lgz_lo += lg2f_(zl); lgz_hi += lg2f_(zh);
            zp = K1;
        }
        STAGE2(x0, z0, r0);
        STAGE2(x1, z1, r1);
    }
    { // tail class 18
        u64 x0, z0, w0;
        STAGE1(x0, z0, w0, 18);
        u64 r0 = rcp_2(w0);
        zp = f2mul(zp, z0);
        float zl, zh; upk2(zp, zl, zh);
        lgz_lo += lg2f_(zl); lgz_hi += lg2f_(zh);
        STAGE2(x0, z0, r0);
    }
#undef STAGE1
#undef STAGE2

    float aU_lo, aU_hi, aX_lo, aX_hi, aP_lo, aP_hi, a0_lo, a0_hi;
    upk2(accU, aU_lo, aU_hi);
    upk2(accX, aX_lo, aX_hi);
    upk2(accP, aP_lo, aP_hi);
    upk2(a0v,  a0_lo, a0_hi);

    // sum_g = sum_p + sum_1/x + sum_poly - 1.5*LN2*lgz + a0 + 19*(1 - 1.5 - C)
    const float KADD = 19.0f * (1.0f - 1.5f - HALF_LN_2PI);

    float xa0 = ex2f(pa0 * LOG2EF);
    float xa1 = ex2f(pa1 * LOG2EF);

    float sumg_lo = fmaf(-1.5f * LN2F, lgz_lo, aP_lo + aX_lo + aU_lo) + a0_lo + KADD;
    float psi0_lo, lg0_lo;
    psi_lg_s(a0_lo, psi0_lo, lg0_lo);
    float kl_lo   = fmaf(-(a0_lo - 19.0f), psi0_lo, lg0_lo) + sumg_lo;
    float loss_lo = fmaf(0.01f, kl_lo, psi0_lo - psi_s(xa0));
    if (ig0) loss_lo = 0.0f;

    float sumg_hi = fmaf(-1.5f * LN2F, lgz_hi, aP_hi + aX_hi + aU_hi) + a0_hi + KADD;
    float psi0_hi, lg0_hi;
    psi_lg_s(a0_hi, psi0_hi, lg0_hi);
    float kl_hi   = fmaf(-(a0_hi - 19.0f), psi0_hi, lg0_hi) + sumg_hi;
    float loss_hi = fmaf(0.01f, kl_hi, psi0_hi - psi_s(xa1));
    if (ig1) loss_hi = 0.0f;

    float loss  = loss_lo + loss_hi;
    int   valid = (ig0 ? 0 : 1) + (ig1 ? 0 : 1);

#pragma unroll
    for (int o = 16; o; o >>= 1) {
        loss  += __shfl_down_sync(0xffffffffu, loss, o);
        valid += __shfl_down_sync(0xffffffffu, valid, o);
    }

    __shared__ float s_l[8];
    __shared__ int   s_v[8];
    int wid = threadIdx.x >> 5;
    int lid = threadIdx.x & 31;
    if (lid == 0) { s_l[wid] = loss; s_v[wid] = valid; }
    __syncthreads();

    if (threadIdx.x == 0) {
        float L = 0.0f;
        int   V = 0;
#pragma unroll
        for (int w = 0; w < 8; ++w) { L += s_l[w]; V += s_v[w]; }
        atomicAdd(&g_sum, (double)L);
        atomicAdd(&g_cnt, (unsigned long long)V);
        __threadfence();
        unsigned int n = atomicAdd(&g_arrive, 1u);
        if (n == (unsigned int)(NBLK_ - 1)) {
            __threadfence();
            double s = *((volatile double*)&g_sum);
            unsigned long long c = *((volatile unsigned long long*)&g_cnt);
            out[0] = (float)(s / (double)c);
            g_sum    = 0.0;
            g_cnt    = 0ull;
            g_arrive = 0u;
        }
    }
}

extern "C" void kernel_launch(void* const* d_in, const int* in_sizes, int n_in,
                              void* d_out, int out_size) {
    const float* pred = (const float*)d_in[0];
    const int*   tgt  = (const int*)d_in[1];
    float*       out  = (float*)d_out;

    bml_main<<<NBLK_, 256>>>(pred, tgt, out);
}

// round 8
// speedup vs baseline: 1.1494x; 1.1494x over previous
#include <cuda_runtime.h>

// BeliefMatchingLoss: pred [8,19,512,512] f32, target [8,512,512] int32 -> scalar f32
// Single-kernel last-block reduction; self-resetting for graph replay.
//
// loss_pix = 0.01*kl + psi(a0) - psi(a_ans)
// kl = lnG(a0) - (a0-19)*psi(a0) + sum_c g(a_c),  a_c = exp(p_c), a0 = sum a_c
// Per-class g via shift-1 (z=x+1, u=1/z), with ln x = p exactly:
//   g ~= p + 1/x + z - 1.5*ln z + (5/6)u + (1/6)u^2 + u^3/90 - (C+1.5)
// Memory: all 19 LDG.64 staged via cp.async into smem (register-free MLP=19),
// one commit_group per class, compute class c under wait_group(18-c) so the
// math drafts directly behind the load stream. Packed 2 px/thread (fma.rn.f32x2).

typedef unsigned long long u64;

#define HW_   (512 * 512)
#define NC_   19
#define NPIX_ (8 * HW_)
#define NTHR_ (NPIX_ / 2)
#define NBLK_ (NTHR_ / 256)

#define LN2F        0.6931471805599453f
#define LOG2EF      1.4426950408889634f
#define HALF_LN_2PI 0.91893853320467274f

__device__ double             g_sum    = 0.0;
__device__ unsigned long long g_cnt    = 0ull;
__device__ unsigned int       g_arrive = 0u;

// ---- packed f32x2 helpers (u64 = {lo,hi} fp32 pair) ----
__device__ __forceinline__ u64 pk2(float a, float b) {
    u64 r; asm("mov.b64 %0,{%1,%2};" : "=l"(r) : "f"(a), "f"(b)); return r;
}
__device__ __forceinline__ void upk2(u64 v, float& a, float& b) {
    asm("mov.b64 {%0,%1},%2;" : "=f"(a), "=f"(b) : "l"(v));
}
__device__ __forceinline__ u64 f2fma(u64 a, u64 b, u64 c) {
    u64 d; asm("fma.rn.f32x2 %0,%1,%2,%3;" : "=l"(d) : "l"(a), "l"(b), "l"(c)); return d;
}
__device__ __forceinline__ u64 f2mul(u64 a, u64 b) {
    u64 d; asm("mul.rn.f32x2 %0,%1,%2;" : "=l"(d) : "l"(a), "l"(b)); return d;
}
__device__ __forceinline__ u64 f2add(u64 a, u64 b) {
    u64 d; asm("add.rn.f32x2 %0,%1,%2;" : "=l"(d) : "l"(a), "l"(b)); return d;
}
__device__ __forceinline__ float ex2f(float x) { float r; asm("ex2.approx.f32 %0,%1;" : "=f"(r) : "f"(x)); return r; }
__device__ __forceinline__ float lg2f_(float x){ float r; asm("lg2.approx.f32 %0,%1;" : "=f"(r) : "f"(x)); return r; }
__device__ __forceinline__ float rcpf_(float x){ float r; asm("rcp.approx.f32 %0,%1;" : "=f"(r) : "f"(x)); return r; }
__device__ __forceinline__ u64 rcp_2(u64 v) { float a, b; upk2(v, a, b); return pk2(rcpf_(a), rcpf_(b)); }

// scalar digamma+lgamma, shift-2 (accurate; once per pixel on a0 >= ~5)
__device__ __forceinline__ void psi_lg_s(float x, float& psi, float& lg) {
    float z   = x + 2.0f;
    float P   = fmaf(x, x, x);
    float r   = rcpf_(P * z);
    float S   = fmaf(2.0f, P, fmaf(3.0f, x, 2.0f)) * r;
    float rz  = P * r;
    float rz2 = rz * rz;
    float lnz = lg2f_(z) * LN2F;
    float lnP = lg2f_(P) * LN2F;
    float c = fmaf(rz, 0.5f, rz2 * fmaf(rz2, -1.0f / 120.0f, 1.0f / 12.0f));
    float t = rz * fmaf(rz2, -1.0f / 360.0f, 1.0f / 12.0f);
    psi = lnz - c - S;
    lg  = fmaf(z - 0.5f, lnz, -z) + HALF_LN_2PI + t - lnP;
}

// scalar digamma only, shift-2 (once per pixel on x_ans)
__device__ __forceinline__ float psi_s(float x) {
    float z   = x + 2.0f;
    float P   = fmaf(x, x, x);
    float r   = rcpf_(P * z);
    float S   = fmaf(2.0f, P, fmaf(3.0f, x, 2.0f)) * r;
    float rz  = P * r;
    float rz2 = rz * rz;
    float c = fmaf(rz, 0.5f, rz2 * fmaf(rz2, -1.0f / 120.0f, 1.0f / 12.0f));
    return lg2f_(z) * LN2F - c - S;
}

__global__ __launch_bounds__(256, 5) void bml_main(const float* __restrict__ pred,
                                                   const int*  __restrict__ tgt,
                                                   float*      __restrict__ out) {
    __shared__ u64 smq[NC_ * 256];   // 38912 B: per-thread staging, slot [c*256 + tid]

    unsigned tid = threadIdx.x;
    int tix = blockIdx.x * 256 + (int)tid;
    int pix = tix * 2;
    int b   = pix >> 18;
    int hw  = pix & (HW_ - 1);
    const float* pp = pred + (size_t)b * NC_ * HW_ + hw;

    unsigned sbase;
    asm("{ .reg .u64 t; cvta.to.shared.u64 t, %1; cvt.u32.u64 %0, t; }"
        : "=r"(sbase) : "l"(smq));
    unsigned stid = sbase + tid * 8u;

    // ---- issue all 19 staged loads, one commit group per class ----
#define CPA(c) asm volatile( \
        "cp.async.ca.shared.global [%0], [%1], 8;\n\t" \
        "cp.async.commit_group;" \
        :: "r"(stid + (unsigned)((c) * 2048)), "l"(pp + (size_t)(c) * HW_) : "memory")
    CPA(0);  CPA(1);  CPA(2);  CPA(3);  CPA(4);  CPA(5);  CPA(6);
    CPA(7);  CPA(8);  CPA(9);  CPA(10); CPA(11); CPA(12); CPA(13);
    CPA(14); CPA(15); CPA(16); CPA(17); CPA(18);
#undef CPA

    int2 tv  = *reinterpret_cast<const int2*>(tgt + pix);
    bool ig0 = (tv.x == 255), ig1 = (tv.y == 255);
    int  ta0 = ig0 ? 0 : tv.x;
    int  ta1 = ig1 ? 0 : tv.y;

    const u64 KL2E = pk2(LOG2EF, LOG2EF);
    const u64 K1   = pk2(1.0f, 1.0f);
    const u64 C90  = pk2(1.0f / 90.0f, 1.0f / 90.0f);
    const u64 C6   = pk2(1.0f / 6.0f, 1.0f / 6.0f);
    const u64 C56  = pk2(5.0f / 6.0f, 5.0f / 6.0f);

    u64 accU = pk2(0.0f, 0.0f);   // sum poly(u)
    u64 accX = accU;              // sum 1/x
    u64 accP = accU;              // sum p (= sum ln x, exact)
    u64 a0v  = accU;              // sum x
    u64 zp   = K1;                // running z product for batched lnz
    float lgz_lo = 0.0f, lgz_hi = 0.0f;

    // load class c from smem, waiting until its group has landed
#define LOADC(pv, c) do {                                                     \
        asm volatile("cp.async.wait_group %0;" :: "n"(18 - (c)) : "memory");  \
        asm volatile("ld.shared.b64 %0,[%1];"                                 \
                     : "=l"(pv) : "r"(stid + (unsigned)((c) * 2048)));        \
    } while (0)

#define STAGE1(xx, zz, ww, c) do {                                            \
        u64 pv; LOADC(pv, c);                                                 \
        accP = f2add(accP, pv);                                               \
        u64 e  = f2mul(pv, KL2E);                                             \
        float el, eh; upk2(e, el, eh);                                        \
        (xx) = pk2(ex2f(el), ex2f(eh));                                       \
        (zz) = f2add((xx), K1);                                               \
        (ww) = f2mul((xx), (zz));                                             \
    } while (0)

#define STAGE2(xx, zz, rr) do {                                               \
        u64 u_ = f2mul((xx), (rr));            /* 1/z */                      \
        u64 ix = f2mul((zz), (rr));            /* 1/x */                      \
        u64 q  = f2fma(u_, C90, C6);                                          \
        q      = f2fma(u_, q, C56);                                           \
        accU   = f2fma(u_, q, accU);                                          \
        accX   = f2add(accX, ix);                                             \
        a0v    = f2add(a0v, (xx));                                            \
    } while (0)

#define PAIR(c0, c1) do {                                                     \
        u64 x0, z0, w0, x1, z1, w1;                                           \
        STAGE1(x0, z0, w0, c0);                                               \
        STAGE1(x1, z1, w1, c1);                                               \
        u64 rr = rcp_2(f2mul(w0, w1));                                        \
        u64 r0 = f2mul(rr, w1);                                               \
        u64 r1 = f2mul(rr, w0);                                               \
        zp = f2mul(zp, f2mul(z0, z1));                                        \
        STAGE2(x0, z0, r0);                                                   \
        STAGE2(x1, z1, r1);                                                   \
    } while (0)

#define ZBATCH() do {                                                         \
        float zl, zh; upk2(zp, zl, zh);                                       \
        lgz_lo += lg2f_(zl); lgz_hi += lg2f_(zh);                             \
        zp = K1;                                                              \
    } while (0)

    PAIR(0, 1);  PAIR(2, 3);  PAIR(4, 5);  PAIR(6, 7);
    ZBATCH();
    PAIR(8, 9);  PAIR(10, 11); PAIR(12, 13); PAIR(14, 15);
    ZBATCH();
    PAIR(16, 17);
    { // tail class 18
        u64 x0, z0, w0;
        STAGE1(x0, z0, w0, 18);
        u64 r0 = rcp_2(w0);
        zp = f2mul(zp, z0);
        ZBATCH();
        STAGE2(x0, z0, r0);
    }
#undef PAIR
#undef STAGE1
#undef STAGE2
#undef ZBATCH
#undef LOADC

    // answer-class logits from smem (all groups complete by now)
    float pa0, pa1;
    asm volatile("ld.shared.f32 %0,[%1];"
                 : "=f"(pa0) : "r"(stid + (unsigned)ta0 * 2048u));
    asm volatile("ld.shared.f32 %0,[%1];"
                 : "=f"(pa1) : "r"(stid + (unsigned)ta1 * 2048u + 4u));

    float aU_lo, aU_hi, aX_lo, aX_hi, aP_lo, aP_hi, a0_lo, a0_hi;
    upk2(accU, aU_lo, aU_hi);
    upk2(accX, aX_lo, aX_hi);
    upk2(accP, aP_lo, aP_hi);
    upk2(a0v,  a0_lo, a0_hi);

    const float KADD = 19.0f * (1.0f - 1.5f - HALF_LN_2PI);

    float xa0 = ex2f(pa0 * LOG2EF);
    float xa1 = ex2f(pa1 * LOG2EF);

    float sumg_lo = fmaf(-1.5f * LN2F, lgz_lo, aP_lo + aX_lo + aU_lo) + a0_lo + KADD;
    float psi0_lo, lg0_lo;
    psi_lg_s(a0_lo, psi0_lo, lg0_lo);
    float kl_lo   = fmaf(-(a0_lo - 19.0f), psi0_lo, lg0_lo) + sumg_lo;
    float loss_lo = fmaf(0.01f, kl_lo, psi0_lo - psi_s(xa0));
    if (ig0) loss_lo = 0.0f;

    float sumg_hi = fmaf(-1.5f * LN2F, lgz_hi, aP_hi + aX_hi + aU_hi) + a0_hi + KADD;
    float psi0_hi, lg0_hi;
    psi_lg_s(a0_hi, psi0_hi, lg0_hi);
    float kl_hi   = fmaf(-(a0_hi - 19.0f), psi0_hi, lg0_hi) + sumg_hi;
    float loss_hi = fmaf(0.01f, kl_hi, psi0_hi - psi_s(xa1));
    if (ig1) loss_hi = 0.0f;

    float loss  = loss_lo + loss_hi;
    int   valid = (ig0 ? 0 : 1) + (ig1 ? 0 : 1);

#pragma unroll
    for (int o = 16; o; o >>= 1) {
        loss  += __shfl_down_sync(0xffffffffu, loss, o);
        valid += __shfl_down_sync(0xffffffffu, valid, o);
    }

    __shared__ float s_l[8];
    __shared__ int   s_v[8];
    int wid = threadIdx.x >> 5;
    int lid = threadIdx.x & 31;
    if (lid == 0) { s_l[wid] = loss; s_v[wid] = valid; }
    __syncthreads();

    if (threadIdx.x == 0) {
        float L = 0.0f;
        int   V = 0;
#pragma unroll
        for (int w = 0; w < 8; ++w) { L += s_l[w]; V += s_v[w]; }
        atomicAdd(&g_sum, (double)L);
        atomicAdd(&g_cnt, (unsigned long long)V);
        __threadfence();
        unsigned int n = atomicAdd(&g_arrive, 1u);
        if (n == (unsigned int)(NBLK_ - 1)) {
            __threadfence();
            double s = *((volatile double*)&g_sum);
            unsigned long long c = *((volatile unsigned long long*)&g_cnt);
            out[0] = (float)(s / (double)c);
            g_sum    = 0.0;
            g_cnt    = 0ull;
            g_arrive = 0u;
        }
    }
}

extern "C" void kernel_launch(void* const* d_in, const int* in_sizes, int n_in,
                              void* d_out, int out_size) {
    const float* pred = (const float*)d_in[0];
    const int*   tgt  = (const int*)d_in[1];
    float*       out  = (float*)d_out;

    bml_main<<<NBLK_, 256>>>(pred, tgt, out);
}

// round 9
// speedup vs baseline: 1.2252x; 1.0659x over previous
#include <cuda_runtime.h>

// BeliefMatchingLoss: pred [8,19,512,512] f32, target [8,512,512] int32 -> scalar f32
// Single-kernel last-block reduction; self-resetting for graph replay.
//
// loss_pix = 0.01*kl + psi(a0) - psi(a_ans)
// kl = lnG(a0) - (a0-19)*psi(a0) + sum_c g(a_c),  a_c = exp(p_c), a0 = sum a_c
// Per-class g via shift-1 (z=x+1, u=1/z, r=1/(x*z)):
//   g ~= p + 1/x + z - 1.5*ln z + (5/6)u + (1/6)u^2 + u^3/90 - (C+1.5)
// Identities used to minimize work:
//   1/x = u + r (exact) -> fold the u part into the poly (5/6 -> 11/6), keep accR += r
//   sum ln z = LN2*sum lg2(W_grp) - sum p, where W_grp = prod(x*z) is ALREADY
//     formed for group-batched reciprocals (sum p accumulated exactly from logits)
//   u^3/90 folded into the u^2 coefficient (1/6 + 1/150)
// Memory: 19 LDG.64 staged via cp.async (one commit group per class), compute
// drafts behind the load stream with wait_group(18-c). Packed 2 px/thread (f32x2).

typedef unsigned long long u64;

#define HW_   (512 * 512)
#define NC_   19
#define NPIX_ (8 * HW_)
#define NTHR_ (NPIX_ / 2)
#define NBLK_ (NTHR_ / 256)

#define LN2F        0.6931471805599453f
#define LOG2EF      1.4426950408889634f
#define HALF_LN_2PI 0.91893853320467274f

__device__ double             g_sum    = 0.0;
__device__ unsigned long long g_cnt    = 0ull;
__device__ unsigned int       g_arrive = 0u;

// ---- packed f32x2 helpers (u64 = {lo,hi} fp32 pair) ----
__device__ __forceinline__ u64 pk2(float a, float b) {
    u64 r; asm("mov.b64 %0,{%1,%2};" : "=l"(r) : "f"(a), "f"(b)); return r;
}
__device__ __forceinline__ void upk2(u64 v, float& a, float& b) {
    asm("mov.b64 {%0,%1},%2;" : "=f"(a), "=f"(b) : "l"(v));
}
__device__ __forceinline__ u64 f2fma(u64 a, u64 b, u64 c) {
    u64 d; asm("fma.rn.f32x2 %0,%1,%2,%3;" : "=l"(d) : "l"(a), "l"(b), "l"(c)); return d;
}
__device__ __forceinline__ u64 f2mul(u64 a, u64 b) {
    u64 d; asm("mul.rn.f32x2 %0,%1,%2;" : "=l"(d) : "l"(a), "l"(b)); return d;
}
__device__ __forceinline__ u64 f2add(u64 a, u64 b) {
    u64 d; asm("add.rn.f32x2 %0,%1,%2;" : "=l"(d) : "l"(a), "l"(b)); return d;
}
__device__ __forceinline__ float ex2f(float x) { float r; asm("ex2.approx.f32 %0,%1;" : "=f"(r) : "f"(x)); return r; }
__device__ __forceinline__ float lg2f_(float x){ float r; asm("lg2.approx.f32 %0,%1;" : "=f"(r) : "f"(x)); return r; }
__device__ __forceinline__ float rcpf_(float x){ float r; asm("rcp.approx.f32 %0,%1;" : "=f"(r) : "f"(x)); return r; }
__device__ __forceinline__ u64 rcp_2(u64 v) { float a, b; upk2(v, a, b); return pk2(rcpf_(a), rcpf_(b)); }

// scalar digamma+lgamma, shift-2 (accurate; once per pixel on a0 >= ~5)
__device__ __forceinline__ void psi_lg_s(float x, float& psi, float& lg) {
    float z   = x + 2.0f;
    float P   = fmaf(x, x, x);
    float r   = rcpf_(P * z);
    float S   = fmaf(2.0f, P, fmaf(3.0f, x, 2.0f)) * r;
    float rz  = P * r;
    float rz2 = rz * rz;
    float lnz = lg2f_(z) * LN2F;
    float lnP = lg2f_(P) * LN2F;
    float c = fmaf(rz, 0.5f, rz2 * fmaf(rz2, -1.0f / 120.0f, 1.0f / 12.0f));
    float t = rz * fmaf(rz2, -1.0f / 360.0f, 1.0f / 12.0f);
    psi = lnz - c - S;
    lg  = fmaf(z - 0.5f, lnz, -z) + HALF_LN_2PI + t - lnP;
}

// scalar digamma only, shift-2 (once per pixel on x_ans)
__device__ __forceinline__ float psi_s(float x) {
    float z   = x + 2.0f;
    float P   = fmaf(x, x, x);
    float r   = rcpf_(P * z);
    float S   = fmaf(2.0f, P, fmaf(3.0f, x, 2.0f)) * r;
    float rz  = P * r;
    float rz2 = rz * rz;
    float c = fmaf(rz, 0.5f, rz2 * fmaf(rz2, -1.0f / 120.0f, 1.0f / 12.0f));
    return lg2f_(z) * LN2F - c - S;
}

__global__ __launch_bounds__(256, 5) void bml_main(const float* __restrict__ pred,
                                                   const int*  __restrict__ tgt,
                                                   float*      __restrict__ out) {
    __shared__ u64 smq[NC_ * 256];   // 38912 B staging, slot [c*256 + tid]

    unsigned tid = threadIdx.x;
    int tix = blockIdx.x * 256 + (int)tid;
    int pix = tix * 2;
    int b   = pix >> 18;
    int hw  = pix & (HW_ - 1);
    const float* pp = pred + (size_t)b * NC_ * HW_ + hw;

    unsigned sbase;
    asm("{ .reg .u64 t; cvta.to.shared.u64 t, %1; cvt.u32.u64 %0, t; }"
        : "=r"(sbase) : "l"(smq));
    unsigned stid = sbase + tid * 8u;

    // ---- issue all 19 staged loads, one commit group per class ----
#define CPA(c) asm volatile( \
        "cp.async.ca.shared.global [%0], [%1], 8;\n\t" \
        "cp.async.commit_group;" \
        :: "r"(stid + (unsigned)((c) * 2048)), "l"(pp + (size_t)(c) * HW_) : "memory")
    CPA(0);  CPA(1);  CPA(2);  CPA(3);  CPA(4);  CPA(5);  CPA(6);
    CPA(7);  CPA(8);  CPA(9);  CPA(10); CPA(11); CPA(12); CPA(13);
    CPA(14); CPA(15); CPA(16); CPA(17); CPA(18);
#undef CPA

    int2 tv  = *reinterpret_cast<const int2*>(tgt + pix);
    bool ig0 = (tv.x == 255), ig1 = (tv.y == 255);
    int  ta0 = ig0 ? 0 : tv.x;
    int  ta1 = ig1 ? 0 : tv.y;

    const u64 KL2E = pk2(LOG2EF, LOG2EF);
    const u64 K1   = pk2(1.0f, 1.0f);
    const u64 Ca   = pk2(11.0f / 6.0f, 11.0f / 6.0f);         // 5/6 + 1 (1/x fold)
    const u64 Cb   = pk2(0.17333333f, 0.17333333f);           // 1/6 + 1/150 (u^3 fold)

    u64 accU = pk2(0.0f, 0.0f);   // sum u*(Ca + Cb*u)
    u64 accR = accU;              // sum r  (r = 1/(x z))
    u64 accP = accU;              // sum p  (= sum ln x, exact)
    u64 a0v  = accU;              // sum x
    float lgw_lo = 0.0f, lgw_hi = 0.0f;  // sum lg2(W_group), W = prod x*z

#define LOADC(pv, c) do {                                                     \
        asm volatile("cp.async.wait_group %0;" :: "n"(18 - (c)) : "memory");  \
        asm volatile("ld.shared.b64 %0,[%1];"                                 \
                     : "=l"(pv) : "r"(stid + (unsigned)((c) * 2048)));        \
    } while (0)

#define STAGE1(xx, ww, c) do {                                                \
        u64 pv; LOADC(pv, c);                                                 \
        accP = f2add(accP, pv);                                               \
        u64 e  = f2mul(pv, KL2E);                                             \
        float el, eh; upk2(e, el, eh);                                        \
        (xx) = pk2(ex2f(el), ex2f(eh));                                       \
        u64 zz = f2add((xx), K1);                                             \
        (ww) = f2mul((xx), zz);                                               \
    } while (0)

#define STAGE2(xx, rr) do {                                                   \
        u64 u_ = f2mul((xx), (rr));                                           \
        u64 q  = f2fma(u_, Cb, Ca);                                           \
        accU   = f2fma(u_, q, accU);                                          \
        accR   = f2add(accR, (rr));                                           \
        a0v    = f2add(a0v, (xx));                                            \
    } while (0)

#define QUAD(c0) do {                                                         \
        u64 x0, w0, x1, w1, x2, w2, x3, w3;                                   \
        STAGE1(x0, w0, (c0) + 0);                                             \
        STAGE1(x1, w1, (c0) + 1);                                             \
        STAGE1(x2, w2, (c0) + 2);                                             \
        STAGE1(x3, w3, (c0) + 3);                                             \
        u64 Wab = f2mul(w0, w1);                                              \
        u64 Wcd = f2mul(w2, w3);                                              \
        u64 Wq  = f2mul(Wab, Wcd);                                            \
        float wl, wh; upk2(Wq, wl, wh);                                       \
        lgw_lo += lg2f_(wl); lgw_hi += lg2f_(wh);                             \
        u64 rr  = rcp_2(Wq);                                                  \
        u64 rab = f2mul(rr, Wcd);                                             \
        u64 rcd = f2mul(rr, Wab);                                             \
        STAGE2(x0, f2mul(rab, w1));                                           \
        STAGE2(x1, f2mul(rab, w0));                                           \
        STAGE2(x2, f2mul(rcd, w3));                                           \
        STAGE2(x3, f2mul(rcd, w2));                                           \
    } while (0)

    QUAD(0); QUAD(4); QUAD(8); QUAD(12);
    { // tail group of 3 (classes 16,17,18)
        u64 x0, w0, x1, w1, x2, w2;
        STAGE1(x0, w0, 16);
        STAGE1(x1, w1, 17);
        STAGE1(x2, w2, 18);
        u64 Wab = f2mul(w0, w1);
        u64 Wq  = f2mul(Wab, w2);
        float wl, wh; upk2(Wq, wl, wh);
        lgw_lo += lg2f_(wl); lgw_hi += lg2f_(wh);
        u64 rr  = rcp_2(Wq);
        u64 rab = f2mul(rr, w2);
        STAGE2(x0, f2mul(rab, w1));
        STAGE2(x1, f2mul(rab, w0));
        STAGE2(x2, f2mul(rr, Wab));
    }
#undef QUAD
#undef STAGE1
#undef STAGE2
#undef LOADC

    // answer-class logits from smem (all groups complete)
    float pa0, pa1;
    asm volatile("ld.shared.f32 %0,[%1];"
                 : "=f"(pa0) : "r"(stid + (unsigned)ta0 * 2048u));
    asm volatile("ld.shared.f32 %0,[%1];"
                 : "=f"(pa1) : "r"(stid + (unsigned)ta1 * 2048u + 4u));

    float aU_lo, aU_hi, aR_lo, aR_hi, aP_lo, aP_hi, a0_lo, a0_hi;
    upk2(accU, aU_lo, aU_hi);
    upk2(accR, aR_lo, aR_hi);
    upk2(accP, aP_lo, aP_hi);
    upk2(a0v,  a0_lo, a0_hi);

    // sum_g = 2.5*sum_p + accR + accU + a0 - 1.5*LN2*lgw + KADD
    //   (sum ln z = LN2*lgw - sum_p;  z-sum and constants folded into KADD)
    const float KADD = 19.0f * (1.0f - 1.5f - HALF_LN_2PI);

    float xa0 = ex2f(pa0 * LOG2EF);
    float xa1 = ex2f(pa1 * LOG2EF);

    float sumg_lo = fmaf(2.5f, aP_lo, fmaf(-1.5f * LN2F, lgw_lo, aR_lo + aU_lo)) + a0_lo + KADD;
    float psi0_lo, lg0_lo;
    psi_lg_s(a0_lo, psi0_lo, lg0_lo);
    float kl_lo   = fmaf(-(a0_lo - 19.0f), psi0_lo, lg0_lo) + sumg_lo;
    float loss_lo = fmaf(0.01f, kl_lo, psi0_lo - psi_s(xa0));
    if (ig0) loss_lo = 0.0f;

    float sumg_hi = fmaf(2.5f, aP_hi, fmaf(-1.5f * LN2F, lgw_hi, aR_hi + aU_hi)) + a0_hi + KADD;
    float psi0_hi, lg0_hi;
    psi_lg_s(a0_hi, psi0_hi, lg0_hi);
    float kl_hi   = fmaf(-(a0_hi - 19.0f), psi0_hi, lg0_hi) + sumg_hi;
    float loss_hi = fmaf(0.01f, kl_hi, psi0_hi - psi_s(xa1));
    if (ig1) loss_hi = 0.0f;

    float loss  = loss_lo + loss_hi;
    int   valid = (ig0 ? 0 : 1) + (ig1 ? 0 : 1);

#pragma unroll
    for (int o = 16; o; o >>= 1) {
        loss  += __shfl_down_sync(0xffffffffu, loss, o);
        valid += __shfl_down_sync(0xffffffffu, valid, o);
    }

    __shared__ float s_l[8];
    __shared__ int   s_v[8];
    int wid = threadIdx.x >> 5;
    int lid = threadIdx.x & 31;
    if (lid == 0) { s_l[wid] = loss; s_v[wid] = valid; }
    __syncthreads();

    if (threadIdx.x == 0) {
        float L = 0.0f;
        int   V = 0;
#pragma unroll
        for (int w = 0; w < 8; ++w) { L += s_l[w]; V += s_v[w]; }
        atomicAdd(&g_sum, (double)L);
        atomicAdd(&g_cnt, (unsigned long long)V);
        __threadfence();
        unsigned int n = atomicAdd(&g_arrive, 1u);
        if (n == (unsigned int)(NBLK_ - 1)) {
            __threadfence();
            double s = *((volatile double*)&g_sum);
            unsigned long long c = *((volatile unsigned long long*)&g_cnt);
            out[0] = (float)(s / (double)c);
            g_sum    = 0.0;
            g_cnt    = 0ull;
            g_arrive = 0u;
        }
    }
}

extern "C" void kernel_launch(void* const* d_in, const int* in_sizes, int n_in,
                              void* d_out, int out_size) {
    const float* pred = (const float*)d_in[0];
    const int*   tgt  = (const int*)d_in[1];
    float*       out  = (float*)d_out;

    bml_main<<<NBLK_, 256>>>(pred, tgt, out);
}